// round 4
// baseline (speedup 1.0000x reference)
#include <cuda_runtime.h>

#define Hc 512
#define Wc 512
#define Bc 8
#define HW (Hc * Wc)

__device__ __forceinline__ float ld_depth(const float* __restrict__ dep, int yi, int xi) {
    // zero-padded out-of-bounds sample (matches reference's valid-mask * value)
    if ((unsigned)yi < (unsigned)Hc && (unsigned)xi < (unsigned)Wc)
        return __ldg(dep + yi * Wc + xi);
    return 0.0f;
}

__global__ __launch_bounds__(256, 4)
void ppd_kernel(const float* __restrict__ depth,
                const float* __restrict__ weight,
                const float* __restrict__ offset,
                float* __restrict__ out)
{
    const int x = blockIdx.x * 32 + threadIdx.x;
    const int y = blockIdx.y * 8  + threadIdx.y;
    const int b = blockIdx.z;
    const int p = y * Wc + x;

    const float* __restrict__ dep = depth  + (size_t)b * HW;
    const float* __restrict__ wp  = weight + (size_t)b * 9  * HW + p;
    const float* __restrict__ op  = offset + (size_t)b * 18 * HW + p;

    // ---- load 9 weights, compute mean ----
    float w[9];
    float mean = 0.0f;
#pragma unroll
    for (int k = 0; k < 9; k++) {
        w[k] = __ldg(wp + k * HW);
        mean += w[k];
    }
    mean *= (1.0f / 9.0f);

    const float ybase = (float)(y - 1);
    const float xbase = (float)(x - 1);

    // ---- 9 deformable bilinear taps ----
    float acc = 0.0f;
#pragma unroll
    for (int k = 0; k < 9; k++) {
        const int ky = k / 3;
        const int kx = k % 3;
        const float dy = __ldg(op + (2 * k)     * HW);
        const float dx = __ldg(op + (2 * k + 1) * HW);

        const float py = dy + ybase + (float)ky;
        const float px = dx + xbase + (float)kx;

        const float fy = floorf(py);
        const float fx = floorf(px);
        const float ty = py - fy;
        const float tx = px - fx;
        const int y0 = (int)fy;
        const int x0 = (int)fx;

        const float v00 = ld_depth(dep, y0,     x0);
        const float v01 = ld_depth(dep, y0,     x0 + 1);
        const float v10 = ld_depth(dep, y0 + 1, x0);
        const float v11 = ld_depth(dep, y0 + 1, x0 + 1);

        const float top = v00 + (v01 - v00) * tx;   // (1-tx)*v00 + tx*v01
        const float bot = v10 + (v11 - v10) * tx;
        const float s   = top + (bot - top) * ty;

        acc = fmaf(s, w[k] - mean, acc);
    }

    out[(size_t)b * HW + p] = acc + __ldg(dep + p);
}

extern "C" void kernel_launch(void* const* d_in, const int* in_sizes, int n_in,
                              void* d_out, int out_size) {
    (void)in_sizes; (void)n_in; (void)out_size;
    const float* depth  = (const float*)d_in[0];
    const float* weight = (const float*)d_in[1];
    const float* offset = (const float*)d_in[2];
    float* out = (float*)d_out;

    dim3 block(32, 8, 1);
    dim3 grid(Wc / 32, Hc / 8, Bc);
    ppd_kernel<<<grid, block>>>(depth, weight, offset, out);
}